// round 11
// baseline (speedup 1.0000x reference)
#include <cuda_runtime.h>
#include <cuda_bf16.h>
#include <cstdint>
#include <math.h>

#define DIMX 4096
#define QKVD 6144
#define KVD  1024
#define SEQT 1024
#define NB 2
#define NHEADS 32
#define HD 128

__device__ float g_qkv[(size_t)NB * SEQT * QKVD];
__device__ float g_att[(size_t)NB * SEQT * DIMX];   // K-permuted layout
__device__ float g_xr[(size_t)NB * SEQT * DIMX];    // tf32-rounded + K-permuted
__device__ float g_w1r[(size_t)QKVD * DIMX];
__device__ float g_w2r[(size_t)DIMX * DIMX];

// ---------------------------------------------------------------------------
__device__ __forceinline__ uint32_t smem_u32(const void* p) {
    uint32_t a;
    asm("{ .reg .u64 t; cvta.to.shared.u64 t, %1; cvt.u32.u64 %0, t; }" : "=r"(a) : "l"(p));
    return a;
}
__device__ __forceinline__ float f2tf32f(float f) {
    uint32_t u;
    asm("cvt.rna.tf32.f32 %0, %1;" : "=r"(u) : "f"(f));
    return __uint_as_float(u);
}
__device__ __forceinline__ void cp16(uint32_t dst, const void* src) {
    asm volatile("cp.async.cg.shared.global [%0], [%1], 16;" :: "r"(dst), "l"(src));
}
#define CP_COMMIT() asm volatile("cp.async.commit_group;" ::: "memory")
#define CP_WAIT(n)  asm volatile("cp.async.wait_group %0;" :: "n"(n) : "memory")

__device__ __forceinline__ void mma_tf32(float* d, const uint32_t* a, const uint32_t* b) {
    asm volatile(
        "mma.sync.aligned.m16n8k8.row.col.f32.tf32.tf32.f32 "
        "{%0,%1,%2,%3}, {%4,%5,%6,%7}, {%8,%9}, {%0,%1,%2,%3};"
        : "+f"(d[0]), "+f"(d[1]), "+f"(d[2]), "+f"(d[3])
        : "r"(a[0]), "r"(a[1]), "r"(a[2]), "r"(a[3]), "r"(b[0]), "r"(b[1]));
}

// ---------------------------------------------------------------------------
// pre-round to tf32 AND interleave each k8 group: mem = [c0,c4,c1,c5,c2,c6,c3,c7]
// ---------------------------------------------------------------------------
__global__ void round_perm(const float* __restrict__ in, float* __restrict__ out, int n8) {
    int i = blockIdx.x * blockDim.x + threadIdx.x;
    if (i < n8) {
        float4 a = ((const float4*)in)[2 * i];
        float4 b = ((const float4*)in)[2 * i + 1];
        float4 o0, o1;
        o0.x = f2tf32f(a.x); o0.y = f2tf32f(b.x);
        o0.z = f2tf32f(a.y); o0.w = f2tf32f(b.y);
        o1.x = f2tf32f(a.z); o1.y = f2tf32f(b.z);
        o1.z = f2tf32f(a.w); o1.w = f2tf32f(b.w);
        ((float4*)out)[2 * i]     = o0;
        ((float4*)out)[2 * i + 1] = o1;
    }
}

// ---------------------------------------------------------------------------
// tf32 mma.sync GEMM: C[M,N] = A[M,K] @ W[N,K]^T + bias[N]
// CTA 128(M) x 256(N), 256 threads (8 warps, 2x4 of 64x64), BK=16,
// 3-stage cp.async, 2 CTAs/SM. APAD=24 (LDS.64 conflict-free: 12g+t mod 16).
// ---------------------------------------------------------------------------
#define APAD 24
#define ATILE_F (128 * APAD)
#define BTILE_F (256 * APAD)
#define STAGE_F (ATILE_F + BTILE_F)
#define STAGES 3
#define GEMM_SMEM (STAGES * STAGE_F * 4)   // 110592 B... (384*24*4*3 = 110592)

__global__ __launch_bounds__(256, 2)
void tf32_gemm(const float* __restrict__ A, const float* __restrict__ W,
               const float* __restrict__ bias, float* __restrict__ C,
               int N, int K) {
    extern __shared__ float sm[];

    const int tid  = threadIdx.x;
    const int wid  = tid / 32;
    const int lane = tid % 32;
    const int wm   = wid >> 2;       // 0..1
    const int wn   = wid & 3;        // 0..3
    const int g    = lane >> 2;      // 0..7
    const int t    = lane & 3;       // 0..3
    const int bx   = blockIdx.x;
    const int by   = blockIdx.y;

    const float* Ab = A + (size_t)(by * 128) * K;
    const float* Wb = W + (size_t)(bx * 256) * K;

    float acc[4][8][4];
    #pragma unroll
    for (int i = 0; i < 4; i++)
        #pragma unroll
        for (int j = 0; j < 8; j++)
            #pragma unroll
            for (int c = 0; c < 4; c++) acc[i][j][c] = 0.0f;

    const int crow = tid >> 2;           // 0..63
    const int ckc  = (tid & 3) * 4;      // 0,4,8,12

    const int ntiles = K / 16;

    auto load_tile = [&](int buf, int kt) {
        float* as = sm + buf * STAGE_F;
        float* bs = as + ATILE_F;
        uint32_t as_u = smem_u32(as);
        uint32_t bs_u = smem_u32(bs);
        const float* Asrc = Ab + kt * 16;
        const float* Bsrc = Wb + kt * 16;
        #pragma unroll
        for (int i = 0; i < 2; i++) {
            int row = crow + i * 64;
            cp16(as_u + (uint32_t)(row * APAD + ckc) * 4u, Asrc + (size_t)row * K + ckc);
        }
        #pragma unroll
        for (int i = 0; i < 4; i++) {
            int row = crow + i * 64;
            cp16(bs_u + (uint32_t)(row * APAD + ckc) * 4u, Bsrc + (size_t)row * K + ckc);
        }
        CP_COMMIT();
    };

    load_tile(0, 0);
    load_tile(1, 1);

    for (int kt = 0; kt < ntiles; kt++) {
        CP_WAIT(1);          // tile kt resident
        __syncthreads();     // visible to all; all warps done with tile kt-1

        if (kt + 2 < ntiles)
            load_tile((kt + 2) % STAGES, kt + 2);   // overlaps compute of kt

        const int buf = kt % STAGES;
        const float* as = sm + buf * STAGE_F + (wm * 64) * APAD;
        const float* bs = sm + buf * STAGE_F + ATILE_F + (wn * 64) * APAD;

        #pragma unroll
        for (int ks = 0; ks < 2; ks++) {
            const int k0 = ks * 8 + 2 * t;   // interleaved: (t, t+4) contiguous
            uint32_t af[4][4], bf[8][2];
            #pragma unroll
            for (int mt = 0; mt < 4; mt++) {
                float2 lo = *(const float2*)(as + (mt * 16 + g) * APAD + k0);
                float2 hi = *(const float2*)(as + (mt * 16 + g + 8) * APAD + k0);
                af[mt][0] = __float_as_uint(lo.x);
                af[mt][1] = __float_as_uint(hi.x);
                af[mt][2] = __float_as_uint(lo.y);
                af[mt][3] = __float_as_uint(hi.y);
            }
            #pragma unroll
            for (int nt = 0; nt < 8; nt++) {
                float2 bb = *(const float2*)(bs + (nt * 8 + g) * APAD + k0);
                bf[nt][0] = __float_as_uint(bb.x);
                bf[nt][1] = __float_as_uint(bb.y);
            }
            #pragma unroll
            for (int mt = 0; mt < 4; mt++)
                #pragma unroll
                for (int nt = 0; nt < 8; nt++)
                    mma_tf32(acc[mt][nt], af[mt], bf[nt]);
        }
    }

    #pragma unroll
    for (int nt = 0; nt < 8; nt++) {
        const int col = bx * 256 + wn * 64 + nt * 8 + 2 * t;
        float2 bv = *(const float2*)(bias + col);
        #pragma unroll
        for (int mt = 0; mt < 4; mt++) {
            const int row = by * 128 + wm * 64 + mt * 16 + g;
            float2 r0, r1;
            r0.x = acc[mt][nt][0] + bv.x;
            r0.y = acc[mt][nt][1] + bv.y;
            r1.x = acc[mt][nt][2] + bv.x;
            r1.y = acc[mt][nt][3] + bv.y;
            *(float2*)(C + (size_t)row * N + col)       = r0;
            *(float2*)(C + (size_t)(row + 8) * N + col) = r1;
        }
    }
}

// ---------------------------------------------------------------------------
// Flash attention, element-wise repeated K/V; permuted att output (unchanged)
// ---------------------------------------------------------------------------
#define AT_BK 32

__global__ __launch_bounds__(256, 2)
void attn_kernel(const float* __restrict__ qkv, float* __restrict__ out) {
    __shared__ float Qs[32][32];
    __shared__ float Kt[32][33];
    __shared__ float Vs[AT_BK][32];

    const int qt   = blockIdx.x;
    const int h    = blockIdx.y;
    const int b    = blockIdx.z;
    const int tid  = threadIdx.x;
    const int wid  = tid / 32;
    const int lane = tid % 32;

    const float* base = qkv + (size_t)b * SEQT * QKVD;
    const float scale = 0.08838834764831845f;

    #pragma unroll
    for (int it = 0; it < 4; it++) {
        int r = it * 8 + wid;
        float4 q4 = *(const float4*)(base + (size_t)(qt * 32 + r) * QKVD + h * HD + lane * 4);
        Qs[r][lane] = (q4.x + q4.y + q4.z + q4.w) * scale;
    }

    float ov[4] = {0.f, 0.f, 0.f, 0.f};
    float m[4] = {-1e30f, -1e30f, -1e30f, -1e30f};
    float l[4] = {0.f, 0.f, 0.f, 0.f};
    const int qr0 = qt * 32 + wid * 4;

    const int ntiles = qt + 1;

    for (int tt = 0; tt < ntiles; tt++) {
        __syncthreads();
        {
            int r  = tid / 8;
            int d4 = (tid % 8) * 4;
            const float* rowp = base + (size_t)(tt * AT_BK + r) * QKVD + DIMX + h * 32 + d4;
            float4 kk = *(const float4*)(rowp);
            float4 vv = *(const float4*)(rowp + KVD);
            Kt[d4 + 0][r] = kk.x; Kt[d4 + 1][r] = kk.y;
            Kt[d4 + 2][r] = kk.z; Kt[d4 + 3][r] = kk.w;
            *(float4*)(&Vs[r][d4]) = vv;
        }
        __syncthreads();

        const int kg = tt * AT_BK + lane;

        #pragma unroll
        for (int i = 0; i < 4; i++) {
            const int q_row = qr0 + i;
            float s = 0.f;
            const float* qrow = Qs[wid * 4 + i];
            #pragma unroll
            for (int j = 0; j < 32; j++)
                s = fmaf(qrow[j], Kt[j][lane], s);
            if (kg > q_row) s = -1e30f;

            float mt = s;
            #pragma unroll
            for (int off = 16; off > 0; off >>= 1)
                mt = fmaxf(mt, __shfl_xor_sync(0xffffffffu, mt, off));
            float m_new = fmaxf(m[i], mt);
            float p = __expf(s - m_new);
            float alpha = __expf(m[i] - m_new);
            m[i] = m_new;

            float ps = p;
            #pragma unroll
            for (int off = 16; off > 0; off >>= 1)
                ps += __shfl_xor_sync(0xffffffffu, ps, off);
            l[i] = l[i] * alpha + ps;

            ov[i] *= alpha;
            #pragma unroll
            for (int k = 0; k < AT_BK; k++) {
                float pk = __shfl_sync(0xffffffffu, p, k);
                ov[i] = fmaf(pk, Vs[k][lane], ov[i]);
            }
        }
    }

    #pragma unroll
    for (int i = 0; i < 4; i++) {
        float r = f2tf32f(ov[i] / l[i]);
        float* po = out + (size_t)(b * SEQT + qr0 + i) * DIMX
                    + h * HD + (lane >> 1) * 8 + (lane & 1);
        po[0] = r; po[2] = r; po[4] = r; po[6] = r;
    }
}

// ---------------------------------------------------------------------------
extern "C" void kernel_launch(void* const* d_in, const int* in_sizes, int n_in,
                              void* d_out, int out_size) {
    const float* x  = (const float*)d_in[0];
    const float* W1 = (const float*)d_in[1];
    const float* b1 = (const float*)d_in[2];
    const float* W2 = (const float*)d_in[3];
    const float* b2 = (const float*)d_in[4];
    float* out = (float*)d_out;

    float *qkv, *att, *xr, *w1r, *w2r;
    cudaGetSymbolAddress((void**)&qkv, g_qkv);
    cudaGetSymbolAddress((void**)&att, g_att);
    cudaGetSymbolAddress((void**)&xr,  g_xr);
    cudaGetSymbolAddress((void**)&w1r, g_w1r);
    cudaGetSymbolAddress((void**)&w2r, g_w2r);

    cudaFuncSetAttribute(tf32_gemm, cudaFuncAttributeMaxDynamicSharedMemorySize, GEMM_SMEM);

    const int M = NB * SEQT;

    {
        int n8 = (M * DIMX) / 8;
        round_perm<<<(n8 + 255) / 256, 256>>>(x, xr, n8);
        n8 = (QKVD * DIMX) / 8;
        round_perm<<<(n8 + 255) / 256, 256>>>(W1, w1r, n8);
        n8 = (DIMX * DIMX) / 8;
        round_perm<<<(n8 + 255) / 256, 256>>>(W2, w2r, n8);
    }

    dim3 g1(QKVD / 256, M / 128);
    tf32_gemm<<<g1, 256, GEMM_SMEM>>>(xr, w1r, b1, qkv, QKVD, DIMX);

    dim3 g2(SEQT / 32, NHEADS, NB);
    attn_kernel<<<g2, 256>>>(qkv, att);

    dim3 g3(DIMX / 256, M / 128);
    tf32_gemm<<<g3, 256, GEMM_SMEM>>>(att, w2r, b2, out, DIMX, DIMX);
}

// round 13
// speedup vs baseline: 4.7940x; 4.7940x over previous
#include <cuda_runtime.h>
#include <cuda_bf16.h>
#include <cstdint>
#include <math.h>

#define DIMX 4096
#define SEQT 1024
#define NB 2
#define NHEADS 32
#define HD 128
#define NQKV 3072          // reduced qkv width: 1024 qred + 1024 K + 1024 V
#define NATT 1024          // reduced attention output width

__device__ float g_qkv[(size_t)NB * SEQT * NQKV];   // plain fp32
__device__ float g_att[(size_t)NB * SEQT * NATT];   // tf32 + k8-permuted
__device__ float g_xr [(size_t)NB * SEQT * DIMX];   // tf32 + k8-permuted
__device__ float g_w1p[(size_t)NQKV * DIMX];        // reduced W1, tf32 + permuted
__device__ float g_w2p[(size_t)DIMX * NATT];        // reduced W2, tf32 + permuted
__device__ float g_b1p[NQKV];

// ---------------------------------------------------------------------------
__device__ __forceinline__ uint32_t smem_u32(const void* p) {
    uint32_t a;
    asm("{ .reg .u64 t; cvta.to.shared.u64 t, %1; cvt.u32.u64 %0, t; }" : "=r"(a) : "l"(p));
    return a;
}
__device__ __forceinline__ float f2tf32f(float f) {
    uint32_t u;
    asm("cvt.rna.tf32.f32 %0, %1;" : "=r"(u) : "f"(f));
    return __uint_as_float(u);
}
__device__ __forceinline__ void cp16(uint32_t dst, const void* src) {
    asm volatile("cp.async.cg.shared.global [%0], [%1], 16;" :: "r"(dst), "l"(src));
}
#define CP_COMMIT() asm volatile("cp.async.commit_group;" ::: "memory")
#define CP_WAIT(n)  asm volatile("cp.async.wait_group %0;" :: "n"(n) : "memory")

__device__ __forceinline__ void mma_tf32(float* d, const uint32_t* a, const uint32_t* b) {
    asm volatile(
        "mma.sync.aligned.m16n8k8.row.col.f32.tf32.tf32.f32 "
        "{%0,%1,%2,%3}, {%4,%5,%6,%7}, {%8,%9}, {%0,%1,%2,%3};"
        : "+f"(d[0]), "+f"(d[1]), "+f"(d[2]), "+f"(d[3])
        : "r"(a[0]), "r"(a[1]), "r"(a[2]), "r"(a[3]), "r"(b[0]), "r"(b[1]));
}

// permutation within a k8 group: mem = [c0,c4,c1,c5,c2,c6,c3,c7]
__device__ __forceinline__ int k8pos(int c) { return (c < 4) ? 2 * c : 2 * (c - 4) + 1; }

// ---------------------------------------------------------------------------
// x: tf32-round + k8-interleave (unchanged from R10)
// ---------------------------------------------------------------------------
__global__ void round_perm(const float* __restrict__ in, float* __restrict__ out, int n8) {
    int i = blockIdx.x * blockDim.x + threadIdx.x;
    if (i < n8) {
        float4 a = ((const float4*)in)[2 * i];
        float4 b = ((const float4*)in)[2 * i + 1];
        float4 o0, o1;
        o0.x = f2tf32f(a.x); o0.y = f2tf32f(b.x);
        o0.z = f2tf32f(a.y); o0.w = f2tf32f(b.y);
        o1.x = f2tf32f(a.z); o1.y = f2tf32f(b.z);
        o1.z = f2tf32f(a.w); o1.w = f2tf32f(b.w);
        ((float4*)out)[2 * i]     = o0;
        ((float4*)out)[2 * i + 1] = o1;
    }
}

// ---------------------------------------------------------------------------
// W1' (3072 x 4096): rows 0..1023 = scale * sum of W1 rows 4j..4j+3 (Q-reduce)
//                    rows 1024..2047 = W1 rows 4096..5119 (K)
//                    rows 2048..3071 = W1 rows 5120..6143 (V)
// tf32-rounded + k8-interleaved. Also builds b1' (fp32, scale folded on Q part).
// One thread per (row, k8-group).
// ---------------------------------------------------------------------------
__global__ void prep_w1(const float* __restrict__ W1, const float* __restrict__ b1,
                        float* __restrict__ W1p, float* __restrict__ b1p) {
    const float scale = 0.08838834764831845f;   // 1/sqrt(128)
    int idx = blockIdx.x * blockDim.x + threadIdx.x;
    if (idx >= NQKV * (DIMX / 8)) return;
    int row = idx / (DIMX / 8);
    int grp = idx % (DIMX / 8);

    float v[8];
    if (row < 1024) {
        const float* s0 = W1 + (size_t)(4 * row) * DIMX + grp * 8;
        #pragma unroll
        for (int c = 0; c < 8; c++)
            v[c] = scale * (s0[c] + s0[DIMX + c] + s0[2 * DIMX + c] + s0[3 * DIMX + c]);
        if (grp == 0)
            b1p[row] = scale * (b1[4 * row] + b1[4 * row + 1] + b1[4 * row + 2] + b1[4 * row + 3]);
    } else {
        int src = (row < 2048) ? (4096 + row - 1024) : (5120 + row - 2048);
        const float* s0 = W1 + (size_t)src * DIMX + grp * 8;
        #pragma unroll
        for (int c = 0; c < 8; c++) v[c] = s0[c];
        if (grp == 0) b1p[row] = b1[src];
    }
    float* o = W1p + (size_t)row * DIMX + grp * 8;
    #pragma unroll
    for (int c = 0; c < 8; c++) o[k8pos(c)] = f2tf32f(v[c]);
}

// ---------------------------------------------------------------------------
// W2' (4096 x 1024): W2red[n][j] = sum_{i<4} W2[n][4j+i], tf32 + k8-interleave.
// ---------------------------------------------------------------------------
__global__ void prep_w2(const float* __restrict__ W2, float* __restrict__ W2p) {
    int idx = blockIdx.x * blockDim.x + threadIdx.x;
    if (idx >= DIMX * (NATT / 8)) return;
    int n   = idx / (NATT / 8);
    int grp = idx % (NATT / 8);
    const float* s0 = W2 + (size_t)n * DIMX + grp * 32;   // 8 reduced cols = 32 orig
    float* o = W2p + (size_t)n * NATT + grp * 8;
    #pragma unroll
    for (int c = 0; c < 8; c++) {
        float v = s0[4 * c] + s0[4 * c + 1] + s0[4 * c + 2] + s0[4 * c + 3];
        o[k8pos(c)] = f2tf32f(v);
    }
}

// ---------------------------------------------------------------------------
// tf32 mma.sync GEMM (R10 config, proven): C = A @ W^T + bias
// CTA 128x128, 128 threads (4 warps, 2x2 of 64x64), BK=32, 2-stage, 2 CTAs/SM.
// A and W must be tf32-rounded + k8-interleaved. C is plain fp32.
// ---------------------------------------------------------------------------
#define APAD 40
#define TILE_F (128 * APAD)
#define STAGE_F (2 * TILE_F)
#define GEMM_SMEM (2 * STAGE_F * 4)        // 81920 B

__global__ __launch_bounds__(128, 2)
void tf32_gemm(const float* __restrict__ A, const float* __restrict__ W,
               const float* __restrict__ bias, float* __restrict__ C,
               int N, int K) {
    extern __shared__ float sm[];

    const int tid  = threadIdx.x;
    const int wid  = tid / 32;
    const int lane = tid % 32;
    const int wm   = wid >> 1;
    const int wn   = wid & 1;
    const int g    = lane >> 2;
    const int t    = lane & 3;
    const int bx   = blockIdx.x;
    const int by   = blockIdx.y;

    const float* Ab = A + (size_t)(by * 128) * K;
    const float* Wb = W + (size_t)(bx * 128) * K;

    float acc[4][8][4];
    #pragma unroll
    for (int i = 0; i < 4; i++)
        #pragma unroll
        for (int j = 0; j < 8; j++)
            #pragma unroll
            for (int c = 0; c < 4; c++) acc[i][j][c] = 0.0f;

    const int crow = tid >> 3;
    const int ckc  = (tid & 7) * 4;

    const int ntiles = K / 32;

    auto load_tile = [&](int buf, int kt) {
        float* as = sm + buf * STAGE_F;
        float* bs = as + TILE_F;
        uint32_t as_u = smem_u32(as);
        uint32_t bs_u = smem_u32(bs);
        const float* Asrc = Ab + kt * 32;
        const float* Bsrc = Wb + kt * 32;
        #pragma unroll
        for (int i = 0; i < 8; i++) {
            int row = crow + i * 16;
            uint32_t doff = (uint32_t)(row * APAD + ckc) * 4u;
            cp16(as_u + doff, Asrc + (size_t)row * K + ckc);
            cp16(bs_u + doff, Bsrc + (size_t)row * K + ckc);
        }
        CP_COMMIT();
    };

    load_tile(0, 0);
    if (ntiles > 1) load_tile(1, 1);

    for (int kt = 0; kt < ntiles; kt++) {
        CP_WAIT(1);
        __syncthreads();

        const int buf = kt & 1;
        const float* as = sm + buf * STAGE_F + (wm * 64) * APAD;
        const float* bs = sm + buf * STAGE_F + TILE_F + (wn * 64) * APAD;

        #pragma unroll
        for (int ks = 0; ks < 4; ks++) {
            const int k0 = ks * 8 + 2 * t;
            uint32_t af[4][4], bf[8][2];
            #pragma unroll
            for (int mt = 0; mt < 4; mt++) {
                float2 lo = *(const float2*)(as + (mt * 16 + g) * APAD + k0);
                float2 hi = *(const float2*)(as + (mt * 16 + g + 8) * APAD + k0);
                af[mt][0] = __float_as_uint(lo.x);
                af[mt][1] = __float_as_uint(hi.x);
                af[mt][2] = __float_as_uint(lo.y);
                af[mt][3] = __float_as_uint(hi.y);
            }
            #pragma unroll
            for (int nt = 0; nt < 8; nt++) {
                float2 bb = *(const float2*)(bs + (nt * 8 + g) * APAD + k0);
                bf[nt][0] = __float_as_uint(bb.x);
                bf[nt][1] = __float_as_uint(bb.y);
            }
            #pragma unroll
            for (int mt = 0; mt < 4; mt++)
                #pragma unroll
                for (int nt = 0; nt < 8; nt++)
                    mma_tf32(acc[mt][nt], af[mt], bf[nt]);
        }

        __syncthreads();
        if (kt + 2 < ntiles)
            load_tile(buf, kt + 2);
    }

    #pragma unroll
    for (int nt = 0; nt < 8; nt++) {
        const int col = bx * 128 + wn * 64 + nt * 8 + 2 * t;
        float2 bv = *(const float2*)(bias + col);
        #pragma unroll
        for (int mt = 0; mt < 4; mt++) {
            const int row = by * 128 + wm * 64 + mt * 16 + g;
            float2 r0, r1;
            r0.x = acc[mt][nt][0] + bv.x;
            r0.y = acc[mt][nt][1] + bv.y;
            r1.x = acc[mt][nt][2] + bv.x;
            r1.y = acc[mt][nt][3] + bv.y;
            *(float2*)(C + (size_t)row * N + col)       = r0;
            *(float2*)(C + (size_t)(row + 8) * N + col) = r1;
        }
    }
}

// ---------------------------------------------------------------------------
// Flash attention (R10 core verbatim). qkv layout: [qred | K | V] x 1024 each.
// Q is pre-reduced & pre-scaled by GEMM1. Output: one value per reduced dim,
// tf32-rounded, stored at the k8-permuted position for GEMM2.
// ---------------------------------------------------------------------------
__global__ __launch_bounds__(256, 2)
void attn_kernel(const float* __restrict__ qkv, float* __restrict__ out) {
    __shared__ float Qs[32][32];
    __shared__ float Kt[32][33];
    __shared__ float Vs[32][32];

    const int qt   = blockIdx.x;
    const int h    = blockIdx.y;
    const int b    = blockIdx.z;
    const int tid  = threadIdx.x;
    const int wid  = tid / 32;
    const int lane = tid % 32;

    const float* base = qkv + (size_t)b * SEQT * NQKV;

    #pragma unroll
    for (int it = 0; it < 4; it++) {
        int r = it * 8 + wid;
        Qs[r][lane] = base[(size_t)(qt * 32 + r) * NQKV + h * 32 + lane];
    }

    float ov[4] = {0.f, 0.f, 0.f, 0.f};
    float m[4] = {-1e30f, -1e30f, -1e30f, -1e30f};
    float l[4] = {0.f, 0.f, 0.f, 0.f};
    const int qr0 = qt * 32 + wid * 4;

    const int ntiles = qt + 1;

    for (int tt = 0; tt < ntiles; tt++) {
        __syncthreads();
        {
            int r  = tid / 8;
            int d4 = (tid % 8) * 4;
            const float* rowp = base + (size_t)(tt * 32 + r) * NQKV + 1024 + h * 32 + d4;
            float4 kk = *(const float4*)(rowp);
            float4 vv = *(const float4*)(rowp + 1024);
            Kt[d4 + 0][r] = kk.x; Kt[d4 + 1][r] = kk.y;
            Kt[d4 + 2][r] = kk.z; Kt[d4 + 3][r] = kk.w;
            *(float4*)(&Vs[r][d4]) = vv;
        }
        __syncthreads();

        const int kg = tt * 32 + lane;

        #pragma unroll
        for (int i = 0; i < 4; i++) {
            const int q_row = qr0 + i;
            float s = 0.f;
            const float* qrow = Qs[wid * 4 + i];
            #pragma unroll
            for (int j = 0; j < 32; j++)
                s = fmaf(qrow[j], Kt[j][lane], s);
            if (kg > q_row) s = -1e30f;

            float mt = s;
            #pragma unroll
            for (int off = 16; off > 0; off >>= 1)
                mt = fmaxf(mt, __shfl_xor_sync(0xffffffffu, mt, off));
            float m_new = fmaxf(m[i], mt);
            float p = __expf(s - m_new);
            float alpha = __expf(m[i] - m_new);
            m[i] = m_new;

            float ps = p;
            #pragma unroll
            for (int off = 16; off > 0; off >>= 1)
                ps += __shfl_xor_sync(0xffffffffu, ps, off);
            l[i] = l[i] * alpha + ps;

            ov[i] *= alpha;
            #pragma unroll
            for (int k = 0; k < 32; k++) {
                float pk = __shfl_sync(0xffffffffu, p, k);
                ov[i] = fmaf(pk, Vs[k][lane], ov[i]);
            }
        }
    }

    // store one value per reduced output dim, at permuted position
    const int j   = h * 32 + lane;           // reduced col 0..1023
    const int pos = (j & ~7) + k8pos(j & 7); // permuted within k8 group
    #pragma unroll
    for (int i = 0; i < 4; i++) {
        float r = f2tf32f(ov[i] / l[i]);
        out[(size_t)(b * SEQT + qr0 + i) * NATT + pos] = r;
    }
}

// ---------------------------------------------------------------------------
extern "C" void kernel_launch(void* const* d_in, const int* in_sizes, int n_in,
                              void* d_out, int out_size) {
    const float* x  = (const float*)d_in[0];
    const float* W1 = (const float*)d_in[1];
    const float* b1 = (const float*)d_in[2];
    const float* W2 = (const float*)d_in[3];
    const float* b2 = (const float*)d_in[4];
    float* out = (float*)d_out;

    float *qkv, *att, *xr, *w1p, *w2p, *b1p;
    cudaGetSymbolAddress((void**)&qkv, g_qkv);
    cudaGetSymbolAddress((void**)&att, g_att);
    cudaGetSymbolAddress((void**)&xr,  g_xr);
    cudaGetSymbolAddress((void**)&w1p, g_w1p);
    cudaGetSymbolAddress((void**)&w2p, g_w2p);
    cudaGetSymbolAddress((void**)&b1p, g_b1p);

    cudaFuncSetAttribute(tf32_gemm, cudaFuncAttributeMaxDynamicSharedMemorySize, GEMM_SMEM);

    const int M = NB * SEQT;   // 2048

    // preprocessing
    {
        int n8 = (M * DIMX) / 8;
        round_perm<<<(n8 + 255) / 256, 256>>>(x, xr, n8);
        int n1 = NQKV * (DIMX / 8);
        prep_w1<<<(n1 + 255) / 256, 256>>>(W1, b1, w1p, b1p);
        int n2 = DIMX * (NATT / 8);
        prep_w2<<<(n2 + 255) / 256, 256>>>(W2, w2p);
    }

    // GEMM1: qkv = xr @ W1p^T + b1p   (2048 x 3072 x 4096)
    dim3 g1(NQKV / 128, M / 128);
    tf32_gemm<<<g1, 128, GEMM_SMEM>>>(xr, w1p, b1p, qkv, NQKV, DIMX);

    // attention
    dim3 g2(SEQT / 32, NHEADS, NB);
    attn_kernel<<<g2, 256>>>(qkv, att);

    // GEMM2: out = att @ W2p^T + b2   (2048 x 4096 x 1024)
    dim3 g3(DIMX / 128, M / 128);
    tf32_gemm<<<g3, 128, GEMM_SMEM>>>(att, w2p, b2, out, DIMX, NATT);
}

// round 14
// speedup vs baseline: 4.9400x; 1.0305x over previous
#include <cuda_runtime.h>
#include <cuda_bf16.h>
#include <cstdint>
#include <math.h>

#define DIMX 4096
#define SEQT 1024
#define NB 2
#define NHEADS 32
#define HD 128
#define NQKV 3072          // reduced qkv width: 1024 qred + 1024 K + 1024 V
#define NATT 1024          // reduced attention output width
#define KSPLIT 3

__device__ float g_qkv[(size_t)NB * SEQT * NQKV];
__device__ float g_att[(size_t)NB * SEQT * NATT];
__device__ float g_xr [(size_t)NB * SEQT * DIMX];
__device__ float g_w1p[(size_t)NQKV * DIMX];
__device__ float g_w2p[(size_t)DIMX * NATT];
__device__ float g_b1p[NQKV];
__device__ float g_part[(size_t)KSPLIT * NB * SEQT * NQKV];   // split-K partials

// ---------------------------------------------------------------------------
__device__ __forceinline__ uint32_t smem_u32(const void* p) {
    uint32_t a;
    asm("{ .reg .u64 t; cvta.to.shared.u64 t, %1; cvt.u32.u64 %0, t; }" : "=r"(a) : "l"(p));
    return a;
}
__device__ __forceinline__ float f2tf32f(float f) {
    uint32_t u;
    asm("cvt.rna.tf32.f32 %0, %1;" : "=r"(u) : "f"(f));
    return __uint_as_float(u);
}
__device__ __forceinline__ void cp16(uint32_t dst, const void* src) {
    asm volatile("cp.async.cg.shared.global [%0], [%1], 16;" :: "r"(dst), "l"(src));
}
#define CP_COMMIT() asm volatile("cp.async.commit_group;" ::: "memory")
#define CP_WAIT(n)  asm volatile("cp.async.wait_group %0;" :: "n"(n) : "memory")

__device__ __forceinline__ void mma_tf32(float* d, const uint32_t* a, const uint32_t* b) {
    asm volatile(
        "mma.sync.aligned.m16n8k8.row.col.f32.tf32.tf32.f32 "
        "{%0,%1,%2,%3}, {%4,%5,%6,%7}, {%8,%9}, {%0,%1,%2,%3};"
        : "+f"(d[0]), "+f"(d[1]), "+f"(d[2]), "+f"(d[3])
        : "r"(a[0]), "r"(a[1]), "r"(a[2]), "r"(a[3]), "r"(b[0]), "r"(b[1]));
}

__device__ __forceinline__ int k8pos(int c) { return (c < 4) ? 2 * c : 2 * (c - 4) + 1; }

// ---------------------------------------------------------------------------
__global__ void round_perm(const float* __restrict__ in, float* __restrict__ out, int n8) {
    int i = blockIdx.x * blockDim.x + threadIdx.x;
    if (i < n8) {
        float4 a = ((const float4*)in)[2 * i];
        float4 b = ((const float4*)in)[2 * i + 1];
        float4 o0, o1;
        o0.x = f2tf32f(a.x); o0.y = f2tf32f(b.x);
        o0.z = f2tf32f(a.y); o0.w = f2tf32f(b.y);
        o1.x = f2tf32f(a.z); o1.y = f2tf32f(b.z);
        o1.z = f2tf32f(a.w); o1.w = f2tf32f(b.w);
        ((float4*)out)[2 * i]     = o0;
        ((float4*)out)[2 * i + 1] = o1;
    }
}

// ---------------------------------------------------------------------------
__global__ void prep_w1(const float* __restrict__ W1, const float* __restrict__ b1,
                        float* __restrict__ W1p, float* __restrict__ b1p) {
    const float scale = 0.08838834764831845f;
    int idx = blockIdx.x * blockDim.x + threadIdx.x;
    if (idx >= NQKV * (DIMX / 8)) return;
    int row = idx / (DIMX / 8);
    int grp = idx % (DIMX / 8);

    float v[8];
    if (row < 1024) {
        const float* s0 = W1 + (size_t)(4 * row) * DIMX + grp * 8;
        #pragma unroll
        for (int c = 0; c < 8; c++)
            v[c] = scale * (s0[c] + s0[DIMX + c] + s0[2 * DIMX + c] + s0[3 * DIMX + c]);
        if (grp == 0)
            b1p[row] = scale * (b1[4 * row] + b1[4 * row + 1] + b1[4 * row + 2] + b1[4 * row + 3]);
    } else {
        int src = (row < 2048) ? (4096 + row - 1024) : (5120 + row - 2048);
        const float* s0 = W1 + (size_t)src * DIMX + grp * 8;
        #pragma unroll
        for (int c = 0; c < 8; c++) v[c] = s0[c];
        if (grp == 0) b1p[row] = b1[src];
    }
    float* o = W1p + (size_t)row * DIMX + grp * 8;
    #pragma unroll
    for (int c = 0; c < 8; c++) o[k8pos(c)] = f2tf32f(v[c]);
}

// ---------------------------------------------------------------------------
__global__ void prep_w2(const float* __restrict__ W2, float* __restrict__ W2p) {
    int idx = blockIdx.x * blockDim.x + threadIdx.x;
    if (idx >= DIMX * (NATT / 8)) return;
    int n   = idx / (NATT / 8);
    int grp = idx % (NATT / 8);
    const float* s0 = W2 + (size_t)n * DIMX + grp * 32;
    float* o = W2p + (size_t)n * NATT + grp * 8;
    #pragma unroll
    for (int c = 0; c < 8; c++) {
        float v = s0[4 * c] + s0[4 * c + 1] + s0[4 * c + 2] + s0[4 * c + 3];
        o[k8pos(c)] = f2tf32f(v);
    }
}

// ---------------------------------------------------------------------------
// split-K reduce: qkv = part0 + part1 + part2 + b1p   (float4)
// ---------------------------------------------------------------------------
__global__ void reduce_k(const float* __restrict__ part, const float* __restrict__ bias,
                         float* __restrict__ out, int n4, int stride_elems) {
    int i = blockIdx.x * blockDim.x + threadIdx.x;
    if (i >= n4) return;
    float4 p0 = ((const float4*)part)[i];
    float4 p1 = ((const float4*)(part + (size_t)stride_elems))[i];
    float4 p2 = ((const float4*)(part + 2 * (size_t)stride_elems))[i];
    int col = (i * 4) % NQKV;
    float4 bv = *(const float4*)(bias + col);
    float4 o;
    o.x = (p0.x + p1.x + p2.x) + bv.x;
    o.y = (p0.y + p1.y + p2.y) + bv.y;
    o.z = (p0.z + p1.z + p2.z) + bv.z;
    o.w = (p0.w + p1.w + p2.w) + bv.w;
    ((float4*)out)[i] = o;
}

// ---------------------------------------------------------------------------
// tf32 mma.sync GEMM (R10 config) with optional split-K via blockIdx.z.
// C = A @ W^T (+ bias if bias != null). gridDim.z partials laid out
// contiguously: Cz = C + z * (gridDim.y*128) * N.
// ---------------------------------------------------------------------------
#define APAD 40
#define TILE_F (128 * APAD)
#define STAGE_F (2 * TILE_F)
#define GEMM_SMEM (2 * STAGE_F * 4)        // 81920 B

__global__ __launch_bounds__(128, 2)
void tf32_gemm(const float* __restrict__ A, const float* __restrict__ W,
               const float* __restrict__ bias, float* __restrict__ C,
               int N, int K) {
    extern __shared__ float sm[];

    const int tid  = threadIdx.x;
    const int wid  = tid / 32;
    const int lane = tid % 32;
    const int wm   = wid >> 1;
    const int wn   = wid & 1;
    const int g    = lane >> 2;
    const int t    = lane & 3;
    const int bx   = blockIdx.x;
    const int by   = blockIdx.y;
    const int bz   = blockIdx.z;

    const int ktot  = K / 32;
    const int kper  = (ktot + (int)gridDim.z - 1) / (int)gridDim.z;
    const int kbeg  = bz * kper;
    const int ntiles = min(kper, ktot - kbeg);

    float* Cz = C + (size_t)bz * (size_t)(gridDim.y * 128) * N;

    const float* Ab = A + (size_t)(by * 128) * K + (size_t)kbeg * 32;
    const float* Wb = W + (size_t)(bx * 128) * K + (size_t)kbeg * 32;

    float acc[4][8][4];
    #pragma unroll
    for (int i = 0; i < 4; i++)
        #pragma unroll
        for (int j = 0; j < 8; j++)
            #pragma unroll
            for (int c = 0; c < 4; c++) acc[i][j][c] = 0.0f;

    const int crow = tid >> 3;
    const int ckc  = (tid & 7) * 4;

    auto load_tile = [&](int buf, int kt) {
        float* as = sm + buf * STAGE_F;
        float* bs = as + TILE_F;
        uint32_t as_u = smem_u32(as);
        uint32_t bs_u = smem_u32(bs);
        const float* Asrc = Ab + kt * 32;
        const float* Bsrc = Wb + kt * 32;
        #pragma unroll
        for (int i = 0; i < 8; i++) {
            int row = crow + i * 16;
            uint32_t doff = (uint32_t)(row * APAD + ckc) * 4u;
            cp16(as_u + doff, Asrc + (size_t)row * K + ckc);
            cp16(bs_u + doff, Bsrc + (size_t)row * K + ckc);
        }
        CP_COMMIT();
    };

    load_tile(0, 0);
    if (ntiles > 1) load_tile(1, 1);

    for (int kt = 0; kt < ntiles; kt++) {
        CP_WAIT(1);
        __syncthreads();

        const int buf = kt & 1;
        const float* as = sm + buf * STAGE_F + (wm * 64) * APAD;
        const float* bs = sm + buf * STAGE_F + TILE_F + (wn * 64) * APAD;

        #pragma unroll
        for (int ks = 0; ks < 4; ks++) {
            const int k0 = ks * 8 + 2 * t;
            uint32_t af[4][4], bf[8][2];
            #pragma unroll
            for (int mt = 0; mt < 4; mt++) {
                float2 lo = *(const float2*)(as + (mt * 16 + g) * APAD + k0);
                float2 hi = *(const float2*)(as + (mt * 16 + g + 8) * APAD + k0);
                af[mt][0] = __float_as_uint(lo.x);
                af[mt][1] = __float_as_uint(hi.x);
                af[mt][2] = __float_as_uint(lo.y);
                af[mt][3] = __float_as_uint(hi.y);
            }
            #pragma unroll
            for (int nt = 0; nt < 8; nt++) {
                float2 bb = *(const float2*)(bs + (nt * 8 + g) * APAD + k0);
                bf[nt][0] = __float_as_uint(bb.x);
                bf[nt][1] = __float_as_uint(bb.y);
            }
            #pragma unroll
            for (int mt = 0; mt < 4; mt++)
                #pragma unroll
                for (int nt = 0; nt < 8; nt++)
                    mma_tf32(acc[mt][nt], af[mt], bf[nt]);
        }

        __syncthreads();
        if (kt + 2 < ntiles)
            load_tile(buf, kt + 2);
    }

    #pragma unroll
    for (int nt = 0; nt < 8; nt++) {
        const int col = bx * 128 + wn * 64 + nt * 8 + 2 * t;
        float2 bv = bias ? *(const float2*)(bias + col) : make_float2(0.f, 0.f);
        #pragma unroll
        for (int mt = 0; mt < 4; mt++) {
            const int row = by * 128 + wm * 64 + mt * 16 + g;
            float2 r0, r1;
            r0.x = acc[mt][nt][0] + bv.x;
            r0.y = acc[mt][nt][1] + bv.y;
            r1.x = acc[mt][nt][2] + bv.x;
            r1.y = acc[mt][nt][3] + bv.y;
            *(float2*)(Cz + (size_t)row * N + col)       = r0;
            *(float2*)(Cz + (size_t)(row + 8) * N + col) = r1;
        }
    }
}

// ---------------------------------------------------------------------------
// Flash attention (R13 arithmetic, loop-interchanged operand delivery).
// Each accumulator chain (s[i], ov[i], m[i], l[i]) sees the identical
// value sequence as R13 — only the loop nesting/data movement changed.
// ---------------------------------------------------------------------------
__global__ __launch_bounds__(256, 2)
void attn_kernel(const float* __restrict__ qkv, float* __restrict__ out) {
    __shared__ float Qs[32][32];
    __shared__ float Kt[32][33];
    __shared__ float Vs[32][32];

    const int qt   = blockIdx.x;
    const int h    = blockIdx.y;
    const int b    = blockIdx.z;
    const int tid  = threadIdx.x;
    const int wid  = tid / 32;
    const int lane = tid % 32;

    const float* base = qkv + (size_t)b * SEQT * NQKV;

    #pragma unroll
    for (int it = 0; it < 4; it++) {
        int r = it * 8 + wid;
        Qs[r][lane] = base[(size_t)(qt * 32 + r) * NQKV + h * 32 + lane];
    }

    float ov[4] = {0.f, 0.f, 0.f, 0.f};
    float m[4] = {-1e30f, -1e30f, -1e30f, -1e30f};
    float l[4] = {0.f, 0.f, 0.f, 0.f};
    const int qr0 = qt * 32 + wid * 4;

    const int ntiles = qt + 1;

    for (int tt = 0; tt < ntiles; tt++) {
        __syncthreads();
        {
            int r  = tid / 8;
            int d4 = (tid % 8) * 4;
            const float* rowp = base + (size_t)(tt * 32 + r) * NQKV + 1024 + h * 32 + d4;
            float4 kk = *(const float4*)(rowp);
            float4 vv = *(const float4*)(rowp + 1024);
            Kt[d4 + 0][r] = kk.x; Kt[d4 + 1][r] = kk.y;
            Kt[d4 + 2][r] = kk.z; Kt[d4 + 3][r] = kk.w;
            *(float4*)(&Vs[r][d4]) = vv;
        }
        __syncthreads();

        const int kg = tt * 32 + lane;
        const float* q0 = Qs[wid * 4 + 0];
        const float* q1 = Qs[wid * 4 + 1];
        const float* q2 = Qs[wid * 4 + 2];
        const float* q3 = Qs[wid * 4 + 3];

        // scores: j outer (Kt value loaded once per j); each s[i] sums j ascending
        float s[4] = {0.f, 0.f, 0.f, 0.f};
        #pragma unroll
        for (int j = 0; j < 32; j++) {
            float kv = Kt[j][lane];
            s[0] = fmaf(q0[j], kv, s[0]);
            s[1] = fmaf(q1[j], kv, s[1]);
            s[2] = fmaf(q2[j], kv, s[2]);
            s[3] = fmaf(q3[j], kv, s[3]);
        }

        // softmax per row (unchanged arithmetic)
        float p[4];
        #pragma unroll
        for (int i = 0; i < 4; i++) {
            float si = s[i];
            if (kg > qr0 + i) si = -1e30f;

            float mt = si;
            #pragma unroll
            for (int off = 16; off > 0; off >>= 1)
                mt = fmaxf(mt, __shfl_xor_sync(0xffffffffu, mt, off));
            float m_new = fmaxf(m[i], mt);
            p[i] = __expf(si - m_new);
            float alpha = __expf(m[i] - m_new);
            m[i] = m_new;

            float ps = p[i];
            #pragma unroll
            for (int off = 16; off > 0; off >>= 1)
                ps += __shfl_xor_sync(0xffffffffu, ps, off);
            l[i] = l[i] * alpha + ps;
            ov[i] *= alpha;
        }

        // PV: k outer (V loaded once per k); each ov[i] sums k ascending
        #pragma unroll
        for (int k = 0; k < 32; k++) {
            float v = Vs[k][lane];
            float pk0 = __shfl_sync(0xffffffffu, p[0], k);
            float pk1 = __shfl_sync(0xffffffffu, p[1], k);
            float pk2 = __shfl_sync(0xffffffffu, p[2], k);
            float pk3 = __shfl_sync(0xffffffffu, p[3], k);
            ov[0] = fmaf(pk0, v, ov[0]);
            ov[1] = fmaf(pk1, v, ov[1]);
            ov[2] = fmaf(pk2, v, ov[2]);
            ov[3] = fmaf(pk3, v, ov[3]);
        }
    }

    const int j   = h * 32 + lane;
    const int pos = (j & ~7) + k8pos(j & 7);
    #pragma unroll
    for (int i = 0; i < 4; i++) {
        float r = f2tf32f(ov[i] / l[i]);
        out[(size_t)(b * SEQT + qr0 + i) * NATT + pos] = r;
    }
}

// ---------------------------------------------------------------------------
extern "C" void kernel_launch(void* const* d_in, const int* in_sizes, int n_in,
                              void* d_out, int out_size) {
    const float* x  = (const float*)d_in[0];
    const float* W1 = (const float*)d_in[1];
    const float* b1 = (const float*)d_in[2];
    const float* W2 = (const float*)d_in[3];
    const float* b2 = (const float*)d_in[4];
    float* out = (float*)d_out;

    float *qkv, *att, *xr, *w1p, *w2p, *b1p, *part;
    cudaGetSymbolAddress((void**)&qkv, g_qkv);
    cudaGetSymbolAddress((void**)&att, g_att);
    cudaGetSymbolAddress((void**)&xr,  g_xr);
    cudaGetSymbolAddress((void**)&w1p, g_w1p);
    cudaGetSymbolAddress((void**)&w2p, g_w2p);
    cudaGetSymbolAddress((void**)&b1p, g_b1p);
    cudaGetSymbolAddress((void**)&part, g_part);

    cudaFuncSetAttribute(tf32_gemm, cudaFuncAttributeMaxDynamicSharedMemorySize, GEMM_SMEM);

    const int M = NB * SEQT;   // 2048

    // preprocessing
    {
        int n8 = (M * DIMX) / 8;
        round_perm<<<(n8 + 255) / 256, 256>>>(x, xr, n8);
        int n1 = NQKV * (DIMX / 8);
        prep_w1<<<(n1 + 255) / 256, 256>>>(W1, b1, w1p, b1p);
        int n2 = DIMX * (NATT / 8);
        prep_w2<<<(n2 + 255) / 256, 256>>>(W2, w2p);
    }

    // GEMM1 split-K=3: partials (2048 x 3072, K=4096)
    dim3 g1(NQKV / 128, M / 128, KSPLIT);
    tf32_gemm<<<g1, 128, GEMM_SMEM>>>(xr, w1p, nullptr, part, NQKV, DIMX);

    // reduce partials + bias -> qkv
    {
        int n4 = (M * NQKV) / 4;
        reduce_k<<<(n4 + 255) / 256, 256>>>(part, b1p, qkv, n4, M * NQKV);
    }

    // attention
    dim3 g2(SEQT / 32, NHEADS, NB);
    attn_kernel<<<g2, 256>>>(qkv, att);

    // GEMM2: out = att @ W2p^T + b2   (2048 x 4096, K=1024)
    dim3 g3(DIMX / 128, M / 128, 1);
    tf32_gemm<<<g3, 128, GEMM_SMEM>>>(att, w2p, b2, out, DIMX, NATT);
}